// round 6
// baseline (speedup 1.0000x reference)
#include <cuda_runtime.h>
#include <math.h>

// ---------------------------------------------------------------------------
// Problem constants
// ---------------------------------------------------------------------------
#define NB     4096
// conv1: 1 -> 32 ch, 28x28, pad 2, pool -> 14x14 (stored zero-padded 18x18)
// conv2: 32 -> 64 ch, 14x14, pad 2, pool -> 7x7
// fc1:   3136 -> 128, relu ; fc2: 128 -> 10

#define P1R 18
#define P1C 18
#define P1A (P1R * P1C)          // 324

typedef unsigned long long u64t;

// ---------------------------------------------------------------------------
// f32x2 packed-FMA helpers (Blackwell sm_103a)
// ---------------------------------------------------------------------------
__device__ __forceinline__ u64t fma2(u64t a, u64t b, u64t c) {
    u64t d;
    asm("fma.rn.f32x2 %0, %1, %2, %3;" : "=l"(d) : "l"(a), "l"(b), "l"(c));
    return d;
}
__device__ __forceinline__ u64t bcast2(float w) {
    unsigned u = __float_as_uint(w);
    u64t r;
    asm("mov.b64 %0, {%1, %1};" : "=l"(r) : "r"(u));
    return r;
}
// {hi(a), lo(b)} -> packed pair (low lane = hi(a), high lane = lo(b))
__device__ __forceinline__ u64t mid2(u64t a, u64t b) {
    unsigned ahi = (unsigned)(a >> 32);
    unsigned blo = (unsigned)b;
    u64t r;
    asm("mov.b64 %0, {%1, %2};" : "=l"(r) : "r"(ahi), "r"(blo));
    return r;
}
__device__ __forceinline__ float lo2(u64t v) { return __uint_as_float((unsigned)v); }
__device__ __forceinline__ float hi2(u64t v) { return __uint_as_float((unsigned)(v >> 32)); }

// ---------------------------------------------------------------------------
// Device scratch
// ---------------------------------------------------------------------------
__device__ float g_K1[32 * 25];                  // [co][tap]
__device__ float g_K2[32 * 64 * 25];             // [ci][co][tap]
__device__ float g_pool1[NB * 32 * P1A];         // conv1 out, relu+pool, ZERO-PADDED 18x18
__device__ float g_pool2[NB * 64 * 7 * 7];
__device__ float g_fc1o[NB * 128];
__device__ float g_fc1wt[3136 * 128];

// ---------------------------------------------------------------------------
// Kernel 1: build dense DCLS kernels
// ---------------------------------------------------------------------------
__global__ void build_kernels_k(const float* __restrict__ w1,
                                const float* __restrict__ p1,
                                const float* __restrict__ w2,
                                const float* __restrict__ p2) {
    int t = blockIdx.x * blockDim.x + threadIdx.x;
    if (t >= 32 + 64 * 32) return;

    float acc[36];
#pragma unroll
    for (int i = 0; i < 36; i++) acc[i] = 0.f;

    if (t < 32) {
        int co = t;
        for (int kc = 0; kc < 16; kc++) {
            float wv = w1[co * 16 + kc];
            float pa = p1[0 * 32 * 16 + co * 16 + kc];
            float pb = p1[1 * 32 * 16 + co * 16 + kc];
            pa = fminf(fmaxf(pa, -2.f), 2.f) + 2.f;
            pb = fminf(fmaxf(pb, -2.f), 2.f) + 2.f;
            int   i1 = (int)floorf(pa), i2 = (int)floorf(pb);
            float r1 = pa - (float)i1,  r2 = pb - (float)i2;
            acc[i1 * 6 + i2]           += wv * (1.f - r1) * (1.f - r2);
            acc[(i1 + 1) * 6 + i2]     += wv * r1 * (1.f - r2);
            acc[i1 * 6 + i2 + 1]       += wv * (1.f - r1) * r2;
            acc[(i1 + 1) * 6 + i2 + 1] += wv * r1 * r2;
        }
        for (int ky = 0; ky < 5; ky++)
            for (int kx = 0; kx < 5; kx++)
                g_K1[co * 25 + ky * 5 + kx] = acc[ky * 6 + kx];
    } else {
        int idx = t - 32;
        int co = idx / 32, ci = idx % 32;
        for (int kc = 0; kc < 32; kc++) {
            float wv = w2[(co * 32 + ci) * 32 + kc];
            float pa = p2[0 * 64 * 32 * 32 + (co * 32 + ci) * 32 + kc];
            float pb = p2[1 * 64 * 32 * 32 + (co * 32 + ci) * 32 + kc];
            pa = fminf(fmaxf(pa, -2.f), 2.f) + 2.f;
            pb = fminf(fmaxf(pb, -2.f), 2.f) + 2.f;
            int   i1 = (int)floorf(pa), i2 = (int)floorf(pb);
            float r1 = pa - (float)i1,  r2 = pb - (float)i2;
            acc[i1 * 6 + i2]           += wv * (1.f - r1) * (1.f - r2);
            acc[(i1 + 1) * 6 + i2]     += wv * r1 * (1.f - r2);
            acc[i1 * 6 + i2 + 1]       += wv * (1.f - r1) * r2;
            acc[(i1 + 1) * 6 + i2 + 1] += wv * r1 * r2;
        }
        for (int ky = 0; ky < 5; ky++)
            for (int kx = 0; kx < 5; kx++)
                g_K2[(ci * 64 + co) * 25 + ky * 5 + kx] = acc[ky * 6 + kx];
    }
}

// ---------------------------------------------------------------------------
// Kernel 2: transpose fc1_w
// ---------------------------------------------------------------------------
__global__ void transpose_fc1w_k(const float* __restrict__ w) {
    int idx = blockIdx.x * blockDim.x + threadIdx.x;
    if (idx < 3136 * 128) {
        int k = idx / 128, n = idx % 128;
        g_fc1wt[idx] = w[n * 3136 + k];
    }
}

// ---------------------------------------------------------------------------
// Kernel 3: conv1 (1->32, pad 2) + bias + relu + pool, FFMA2 row-stationary.
// 448 threads = (yp in 0..13) x (co in 0..31); two column-halves sequential.
// Output in zero-padded 18x18 layout.
// ---------------------------------------------------------------------------
#define C1_THREADS 448

__global__ __launch_bounds__(C1_THREADS, 1) void conv1_k(const float* __restrict__ x,
                                                         const float* __restrict__ b1) {
    __shared__ float xs[32 * 32];   // rows/cols -2..29 (zero-padded)
    __shared__ float ks[800];       // 32 x 25
    int b = blockIdx.x;
    int t = threadIdx.x;
    const float* xp = x + b * 784;
    for (int i = t; i < 1024; i += C1_THREADS) {
        int r = (i >> 5) - 2, c = (i & 31) - 2;
        xs[i] = (r >= 0 && r < 28 && c >= 0 && c < 28) ? xp[r * 28 + c] : 0.f;
    }
    for (int i = t; i < 800; i += C1_THREADS) ks[i] = g_K1[i];

    // zero border rows of padded output: pr in {0,1,16,17}, all pc, all 32 ci
    float* bout = g_pool1 + b * (32 * P1A);
    for (int i = t; i < 2304; i += C1_THREADS) {
        int cii = i / 72, rem = i % 72;
        int rr = rem / 18, pc = rem % 18;
        int pr = (rr < 2) ? rr : (14 + rr);
        bout[cii * P1A + pr * P1C + pc] = 0.f;
    }
    __syncthreads();

    int yp = t >> 5;     // 0..13  (pooled row)
    int co = t & 31;     // 0..31
    int prow0 = 2 * yp;  // first padded input row used
    const float* wp = ks + co * 25;
    float bias = b1[co];
    float* outp = bout + co * P1A + (yp + 2) * P1C;

#pragma unroll 1
    for (int half = 0; half < 2; half++) {
        int x0 = half * 14;
        u64t accA[7], accB[7];
#pragma unroll
        for (int p = 0; p < 7; p++) { accA[p] = 0ull; accB[p] = 0ull; }
        u64t wA[5], wB[5];
#pragma unroll
        for (int kx = 0; kx < 5; kx++) { wA[kx] = 0ull; wB[kx] = 0ull; }

#pragma unroll
        for (int j = 0; j < 6; j++) {
            const u64t* rp = (const u64t*)(xs + (prow0 + j) * 32 + x0);
            u64t e[9];
#pragma unroll
            for (int c = 0; c < 9; c++) e[c] = rp[c];
            u64t o[8];
#pragma unroll
            for (int c = 0; c < 8; c++) o[c] = mid2(e[c], e[c + 1]);

            if (j < 5) {
#pragma unroll
                for (int kx = 0; kx < 5; kx++) wA[kx] = bcast2(wp[j * 5 + kx]);
#pragma unroll
                for (int p = 0; p < 7; p++) accA[p] = fma2(e[p],     wA[0], accA[p]);
#pragma unroll
                for (int p = 0; p < 7; p++) accA[p] = fma2(o[p],     wA[1], accA[p]);
#pragma unroll
                for (int p = 0; p < 7; p++) accA[p] = fma2(e[p + 1], wA[2], accA[p]);
#pragma unroll
                for (int p = 0; p < 7; p++) accA[p] = fma2(o[p + 1], wA[3], accA[p]);
#pragma unroll
                for (int p = 0; p < 7; p++) accA[p] = fma2(e[p + 2], wA[4], accA[p]);
            }
            if (j >= 1) {
#pragma unroll
                for (int p = 0; p < 7; p++) accB[p] = fma2(e[p],     wB[0], accB[p]);
#pragma unroll
                for (int p = 0; p < 7; p++) accB[p] = fma2(o[p],     wB[1], accB[p]);
#pragma unroll
                for (int p = 0; p < 7; p++) accB[p] = fma2(e[p + 1], wB[2], accB[p]);
#pragma unroll
                for (int p = 0; p < 7; p++) accB[p] = fma2(o[p + 1], wB[3], accB[p]);
#pragma unroll
                for (int p = 0; p < 7; p++) accB[p] = fma2(e[p + 2], wB[4], accB[p]);
            }
#pragma unroll
            for (int kx = 0; kx < 5; kx++) wB[kx] = wA[kx];
        }

        // pool(2x2 over the two conv rows) + bias + relu, write interior cols
#pragma unroll
        for (int p = 0; p < 7; p++) {
            float m = fmaxf(fmaxf(lo2(accA[p]), hi2(accA[p])),
                            fmaxf(lo2(accB[p]), hi2(accB[p])));
            outp[half * 7 + p + 2] = fmaxf(m + bias, 0.f);
        }
        // border cols of this padded row
        if (half == 0) { outp[0] = 0.f; outp[1] = 0.f; }
        else           { outp[16] = 0.f; outp[17] = 0.f; }
    }
}

// ---------------------------------------------------------------------------
// Kernel 4: conv2 (32->64, pad 2) + bias + relu + pool, FFMA2 row-stationary.
// 448 threads = (yp in 0..6) x (co in 0..63). Input pre-padded 18x18/ci.
// Even input pairs via broadcast LDS.64; odd pairs 1 MOV; weights 1 MOV pack.
// 16-ci weight chunks in smem (total 143.9 KB, 1 CTA/SM).
// ---------------------------------------------------------------------------
#define C2_THREADS 448
#define C2_IN_FLOATS (32 * P1A)                  // 10368
#define C2_WCHUNK_CI 16
#define C2_W_FLOATS (C2_WCHUNK_CI * 64 * 25)     // 25600
#define C2_SMEM_FLOATS (C2_IN_FLOATS + C2_W_FLOATS)

__global__ __launch_bounds__(C2_THREADS, 1) void conv2_k(const float* __restrict__ b2) {
    extern __shared__ float sm[];
    float* in_s = sm;                 // 32 x 324 padded input
    float* ws   = sm + C2_IN_FLOATS;  // 16 x 64 x 25 weight chunk

    int b = blockIdx.x;
    int t = threadIdx.x;
    const float* ip = g_pool1 + b * C2_IN_FLOATS;
    for (int i = t; i < C2_IN_FLOATS; i += C2_THREADS) in_s[i] = ip[i];

    int yp = t / 64;     // 0..6
    int co = t % 64;     // 0..63
    int prow0 = 2 * yp;

    u64t accA[7], accB[7];
#pragma unroll
    for (int p = 0; p < 7; p++) { accA[p] = 0ull; accB[p] = 0ull; }

#pragma unroll 1
    for (int chunk = 0; chunk < 2; chunk++) {
        __syncthreads();
        const float* wsrc = g_K2 + chunk * C2_W_FLOATS;
        for (int i = t; i < C2_W_FLOATS; i += C2_THREADS) ws[i] = wsrc[i];
        __syncthreads();

#pragma unroll 1
        for (int cil = 0; cil < C2_WCHUNK_CI; cil++) {
            int ci = chunk * C2_WCHUNK_CI + cil;
            const float* inc = in_s + ci * P1A;
            const float* wp  = ws + (cil * 64 + co) * 25;

            u64t wA[5], wB[5];
#pragma unroll
            for (int kx = 0; kx < 5; kx++) { wA[kx] = 0ull; wB[kx] = 0ull; }

#pragma unroll
            for (int j = 0; j < 6; j++) {
                const u64t* rp = (const u64t*)(inc + (prow0 + j) * P1C);
                u64t e[9];
#pragma unroll
                for (int c = 0; c < 9; c++) e[c] = rp[c];
                u64t o[8];
#pragma unroll
                for (int c = 0; c < 8; c++) o[c] = mid2(e[c], e[c + 1]);

                if (j < 5) {
#pragma unroll
                    for (int kx = 0; kx < 5; kx++) wA[kx] = bcast2(wp[j * 5 + kx]);
#pragma unroll
                    for (int p = 0; p < 7; p++) accA[p] = fma2(e[p],     wA[0], accA[p]);
#pragma unroll
                    for (int p = 0; p < 7; p++) accA[p] = fma2(o[p],     wA[1], accA[p]);
#pragma unroll
                    for (int p = 0; p < 7; p++) accA[p] = fma2(e[p + 1], wA[2], accA[p]);
#pragma unroll
                    for (int p = 0; p < 7; p++) accA[p] = fma2(o[p + 1], wA[3], accA[p]);
#pragma unroll
                    for (int p = 0; p < 7; p++) accA[p] = fma2(e[p + 2], wA[4], accA[p]);
                }
                if (j >= 1) {
#pragma unroll
                    for (int p = 0; p < 7; p++) accB[p] = fma2(e[p],     wB[0], accB[p]);
#pragma unroll
                    for (int p = 0; p < 7; p++) accB[p] = fma2(o[p],     wB[1], accB[p]);
#pragma unroll
                    for (int p = 0; p < 7; p++) accB[p] = fma2(e[p + 1], wB[2], accB[p]);
#pragma unroll
                    for (int p = 0; p < 7; p++) accB[p] = fma2(o[p + 1], wB[3], accB[p]);
#pragma unroll
                    for (int p = 0; p < 7; p++) accB[p] = fma2(e[p + 2], wB[4], accB[p]);
                }
#pragma unroll
                for (int kx = 0; kx < 5; kx++) wB[kx] = wA[kx];
            }
        }
    }

    float bias = b2[co];
    float* op = g_pool2 + (b * 64 + co) * 49 + yp * 7;
#pragma unroll
    for (int xp = 0; xp < 7; xp++) {
        float m = fmaxf(fmaxf(lo2(accA[xp]), hi2(accA[xp])),
                        fmaxf(lo2(accB[xp]), hi2(accB[xp])));
        op[xp] = fmaxf(m + bias, 0.f);
    }
}

// ---------------------------------------------------------------------------
// Kernel 5: fc1 GEMM (unchanged)
// ---------------------------------------------------------------------------
__global__ __launch_bounds__(256) void fc1_k(const float* __restrict__ fc1_b) {
    __shared__ float As[32 * 32];
    __shared__ float Bs[32 * 128];

    int m0 = blockIdx.x * 32;
    int tid = threadIdx.x;
    int tm = tid / 32;
    int tn = tid % 32;

    float c[4][4];
#pragma unroll
    for (int i = 0; i < 4; i++)
#pragma unroll
        for (int j = 0; j < 4; j++) c[i][j] = 0.f;

    const float* A = g_pool2;

    for (int k0 = 0; k0 < 3136; k0 += 32) {
#pragma unroll
        for (int l = 0; l < 4; l++) {
            int i = tid + l * 256;
            int mm = i / 32, kk = i % 32;
            As[mm * 32 + kk] = A[(m0 + mm) * 3136 + k0 + kk];
        }
#pragma unroll
        for (int l = 0; l < 16; l++) {
            int i = tid + l * 256;
            int kk = i / 128, n = i % 128;
            Bs[kk * 128 + n] = g_fc1wt[(k0 + kk) * 128 + n];
        }
        __syncthreads();

#pragma unroll
        for (int kk = 0; kk < 32; kk++) {
            float a0 = As[(tm * 4 + 0) * 32 + kk];
            float a1 = As[(tm * 4 + 1) * 32 + kk];
            float a2 = As[(tm * 4 + 2) * 32 + kk];
            float a3 = As[(tm * 4 + 3) * 32 + kk];
            float4 bv = *(const float4*)&Bs[kk * 128 + tn * 4];
            c[0][0] += a0 * bv.x; c[0][1] += a0 * bv.y; c[0][2] += a0 * bv.z; c[0][3] += a0 * bv.w;
            c[1][0] += a1 * bv.x; c[1][1] += a1 * bv.y; c[1][2] += a1 * bv.z; c[1][3] += a1 * bv.w;
            c[2][0] += a2 * bv.x; c[2][1] += a2 * bv.y; c[2][2] += a2 * bv.z; c[2][3] += a2 * bv.w;
            c[3][0] += a3 * bv.x; c[3][1] += a3 * bv.y; c[3][2] += a3 * bv.z; c[3][3] += a3 * bv.w;
        }
        __syncthreads();
    }

#pragma unroll
    for (int j = 0; j < 4; j++) {
        int m = m0 + tm * 4 + j;
#pragma unroll
        for (int jj = 0; jj < 4; jj++) {
            int n = tn * 4 + jj;
            g_fc1o[m * 128 + n] = fmaxf(c[j][jj] + fc1_b[n], 0.f);
        }
    }
}

// ---------------------------------------------------------------------------
// Kernel 6: fc2 (unchanged)
// ---------------------------------------------------------------------------
__global__ __launch_bounds__(256) void fc2_k(const float* __restrict__ fc2_w,
                                             const float* __restrict__ fc2_b,
                                             float* __restrict__ out) {
    int idx = blockIdx.x * blockDim.x + threadIdx.x;
    if (idx >= NB * 10) return;
    int m = idx / 10, n = idx % 10;
    const float4* h = (const float4*)(g_fc1o + m * 128);
    const float4* w = (const float4*)(fc2_w + n * 128);
    float s = 0.f;
#pragma unroll
    for (int i = 0; i < 32; i++) {
        float4 a = h[i], bb = w[i];
        s += a.x * bb.x + a.y * bb.y + a.z * bb.z + a.w * bb.w;
    }
    out[idx] = s + fc2_b[n];
}

// ---------------------------------------------------------------------------
// Launch
// ---------------------------------------------------------------------------
extern "C" void kernel_launch(void* const* d_in, const int* in_sizes, int n_in,
                              void* d_out, int out_size) {
    const float* x     = (const float*)d_in[0];
    const float* w1    = (const float*)d_in[1];
    const float* p1    = (const float*)d_in[2];
    const float* b1    = (const float*)d_in[3];
    const float* w2    = (const float*)d_in[4];
    const float* p2    = (const float*)d_in[5];
    const float* b2    = (const float*)d_in[6];
    const float* fc1w  = (const float*)d_in[7];
    const float* fc1b  = (const float*)d_in[8];
    const float* fc2w  = (const float*)d_in[9];
    const float* fc2b  = (const float*)d_in[10];
    float* out = (float*)d_out;

    cudaFuncSetAttribute(conv2_k, cudaFuncAttributeMaxDynamicSharedMemorySize,
                         C2_SMEM_FLOATS * 4);

    build_kernels_k<<<(32 + 64 * 32 + 127) / 128, 128>>>(w1, p1, w2, p2);
    transpose_fc1w_k<<<(3136 * 128 + 255) / 256, 256>>>(fc1w);
    conv1_k<<<NB, C1_THREADS>>>(x, b1);
    conv2_k<<<NB, C2_THREADS, C2_SMEM_FLOATS * 4>>>(b2);
    fc1_k<<<NB / 32, 256>>>(fc1b);
    fc2_k<<<(NB * 10 + 255) / 256, 256>>>(fc2w, fc2b, out);
}

// round 7
// speedup vs baseline: 1.2196x; 1.2196x over previous
#include <cuda_runtime.h>
#include <math.h>

// ---------------------------------------------------------------------------
// Problem constants
// ---------------------------------------------------------------------------
#define NB     4096
// conv1: 1 -> 32 ch, 28x28, pad 2, pool -> 14x14 (stored zero-padded 18x18)
// conv2: 32 -> 64 ch, 14x14, pad 2, pool -> 7x7
// fc1:   3136 -> 128, relu ; fc2: 128 -> 10

#define P1R 18
#define P1C 18
#define P1A (P1R * P1C)          // 324

// ---------------------------------------------------------------------------
// cp.async helpers
// ---------------------------------------------------------------------------
__device__ __forceinline__ unsigned smem_u32(const void* p) {
    unsigned a;
    asm("{ .reg .u64 t; cvta.to.shared.u64 t, %1; cvt.u32.u64 %0, t; }"
        : "=r"(a) : "l"(p));
    return a;
}
__device__ __forceinline__ void cpa16(unsigned s, const void* g) {
    asm volatile("cp.async.cg.shared.global [%0], [%1], 16;" :: "r"(s), "l"(g));
}
#define CP_COMMIT() asm volatile("cp.async.commit_group;")
#define CP_WAIT1()  asm volatile("cp.async.wait_group 1;" ::: "memory")

// ---------------------------------------------------------------------------
// Device scratch
// ---------------------------------------------------------------------------
__device__ float g_K1[32 * 25];                  // [co][tap]
__device__ float g_K2[32 * 64 * 25];             // [ci][co][tap]
__device__ float g_pool1[NB * 32 * P1A];         // conv1 out, relu+pool, ZERO-PADDED 18x18
__device__ float g_pool2[NB * 64 * 7 * 7];
__device__ float g_fc1o[NB * 128];
__device__ float g_fc1wt[3136 * 128];

// ---------------------------------------------------------------------------
// Kernel 1: build dense DCLS kernels
// ---------------------------------------------------------------------------
__global__ void build_kernels_k(const float* __restrict__ w1,
                                const float* __restrict__ p1,
                                const float* __restrict__ w2,
                                const float* __restrict__ p2) {
    int t = blockIdx.x * blockDim.x + threadIdx.x;
    if (t >= 32 + 64 * 32) return;

    float acc[36];
#pragma unroll
    for (int i = 0; i < 36; i++) acc[i] = 0.f;

    if (t < 32) {
        int co = t;
        for (int kc = 0; kc < 16; kc++) {
            float wv = w1[co * 16 + kc];
            float pa = p1[0 * 32 * 16 + co * 16 + kc];
            float pb = p1[1 * 32 * 16 + co * 16 + kc];
            pa = fminf(fmaxf(pa, -2.f), 2.f) + 2.f;
            pb = fminf(fmaxf(pb, -2.f), 2.f) + 2.f;
            int   i1 = (int)floorf(pa), i2 = (int)floorf(pb);
            float r1 = pa - (float)i1,  r2 = pb - (float)i2;
            acc[i1 * 6 + i2]           += wv * (1.f - r1) * (1.f - r2);
            acc[(i1 + 1) * 6 + i2]     += wv * r1 * (1.f - r2);
            acc[i1 * 6 + i2 + 1]       += wv * (1.f - r1) * r2;
            acc[(i1 + 1) * 6 + i2 + 1] += wv * r1 * r2;
        }
        for (int ky = 0; ky < 5; ky++)
            for (int kx = 0; kx < 5; kx++)
                g_K1[co * 25 + ky * 5 + kx] = acc[ky * 6 + kx];
    } else {
        int idx = t - 32;
        int co = idx / 32, ci = idx % 32;
        for (int kc = 0; kc < 32; kc++) {
            float wv = w2[(co * 32 + ci) * 32 + kc];
            float pa = p2[0 * 64 * 32 * 32 + (co * 32 + ci) * 32 + kc];
            float pb = p2[1 * 64 * 32 * 32 + (co * 32 + ci) * 32 + kc];
            pa = fminf(fmaxf(pa, -2.f), 2.f) + 2.f;
            pb = fminf(fmaxf(pb, -2.f), 2.f) + 2.f;
            int   i1 = (int)floorf(pa), i2 = (int)floorf(pb);
            float r1 = pa - (float)i1,  r2 = pb - (float)i2;
            acc[i1 * 6 + i2]           += wv * (1.f - r1) * (1.f - r2);
            acc[(i1 + 1) * 6 + i2]     += wv * r1 * (1.f - r2);
            acc[i1 * 6 + i2 + 1]       += wv * (1.f - r1) * r2;
            acc[(i1 + 1) * 6 + i2 + 1] += wv * r1 * r2;
        }
        // store as [ci][co][q] so conv2's smem chunk copy is a straight memcpy
        for (int ky = 0; ky < 5; ky++)
            for (int kx = 0; kx < 5; kx++)
                g_K2[(ci * 64 + co) * 25 + ky * 5 + kx] = acc[ky * 6 + kx];
    }
}

// ---------------------------------------------------------------------------
// Kernel 2: transpose fc1_w (128 x 3136) -> g_fc1wt (3136 x 128)
// ---------------------------------------------------------------------------
__global__ void transpose_fc1w_k(const float* __restrict__ w) {
    int idx = blockIdx.x * blockDim.x + threadIdx.x;
    if (idx < 3136 * 128) {
        int k = idx / 128, n = idx % 128;
        g_fc1wt[idx] = w[n * 3136 + k];
    }
}

// ---------------------------------------------------------------------------
// Kernel 3: conv1 (1->32, pad 2) + bias + relu + 2x2 maxpool, fused.
// (round-3 version: padded 32x32 image in smem, padded 18x18 output)
// ---------------------------------------------------------------------------
__global__ __launch_bounds__(256) void conv1_k(const float* __restrict__ x,
                                               const float* __restrict__ b1) {
    __shared__ float xs[32 * 32];   // rows/cols -2..29
    __shared__ float ks[800];       // 32 x 25
    int b = blockIdx.x;
    const float* xp = x + b * 784;
    for (int i = threadIdx.x; i < 1024; i += 256) {
        int r = i / 32 - 2, c = i % 32 - 2;
        xs[i] = (r >= 0 && r < 28 && c >= 0 && c < 28) ? xp[r * 28 + c] : 0.f;
    }
    for (int i = threadIdx.x; i < 800; i += 256) ks[i] = g_K1[i];
    __syncthreads();

    float* outp = g_pool1 + b * 32 * P1A;
    for (int o = threadIdx.x; o < 32 * P1A; o += 256) {
        int co = o / P1A, m = o % P1A;
        int pr = m / P1C, pc = m % P1C;
        int yp = pr - 2,  xq = pc - 2;
        float outv = 0.f;
        if (yp >= 0 && yp < 14 && xq >= 0 && xq < 14) {
            int y0 = 2 * yp, x0 = 2 * xq;
            float patch[36];
#pragma unroll
            for (int dy = 0; dy < 6; dy++)
#pragma unroll
                for (int dx = 0; dx < 6; dx++)
                    patch[dy * 6 + dx] = xs[(y0 + dy) * 32 + (x0 + dx)];
            const float* kk = &ks[co * 25];
            float v0 = 0.f, v1 = 0.f, v2 = 0.f, v3 = 0.f;
#pragma unroll
            for (int ky = 0; ky < 5; ky++) {
#pragma unroll
                for (int kx = 0; kx < 5; kx++) {
                    float wv = kk[ky * 5 + kx];
                    v0 += wv * patch[(ky)     * 6 + kx];
                    v1 += wv * patch[(ky)     * 6 + kx + 1];
                    v2 += wv * patch[(ky + 1) * 6 + kx];
                    v3 += wv * patch[(ky + 1) * 6 + kx + 1];
                }
            }
            float mx = fmaxf(fmaxf(v0, v1), fmaxf(v2, v3)) + b1[co];
            outv = fmaxf(mx, 0.f);
        }
        outp[o] = outv;
    }
}

// ---------------------------------------------------------------------------
// Kernel 4: conv2 (32->64, pad 2) + bias + relu + pool, scalar row-stationary
// (round-3 math) + cp.async DOUBLE-BUFFERED weight pipeline.
// 448 threads = (yp 0..6) x (co 0..63). 8 chunks of 4 ci; two 25.6 KB weight
// buffers; chunk c+2 prefetched during compute of chunk c. Input tile fetched
// via cp.async in the first group. smem = 92.7 KB -> 2 CTAs/SM.
// ---------------------------------------------------------------------------
#define C2_THREADS 448
#define C2_IN_FLOATS (32 * P1A)                 // 10368 floats = 41472 B
#define C2_WCHUNK_CI 4
#define C2_W_FLOATS (C2_WCHUNK_CI * 64 * 25)    // 6400 floats = 25600 B
#define C2_NCHUNK 8
#define C2_SMEM_FLOATS (C2_IN_FLOATS + 2 * C2_W_FLOATS)   // 23168 floats

__global__ __launch_bounds__(C2_THREADS, 2) void conv2_k(const float* __restrict__ b2) {
    extern __shared__ float sm[];
    float* in_s = sm;                              // 32 x 324 padded input
    float* wbuf[2] = { sm + C2_IN_FLOATS,
                       sm + C2_IN_FLOATS + C2_W_FLOATS };

    int b = blockIdx.x;
    int t = threadIdx.x;

    unsigned in_sa = smem_u32(in_s);
    unsigned wba[2] = { smem_u32(wbuf[0]), smem_u32(wbuf[1]) };

    // group 0: input tile + weight chunk 0
    {
        const char* ip = (const char*)(g_pool1 + b * C2_IN_FLOATS);
        for (int i = t; i < C2_IN_FLOATS / 4; i += C2_THREADS)
            cpa16(in_sa + i * 16, ip + i * 16);
        const char* wp0 = (const char*)(g_K2);
        for (int i = t; i < C2_W_FLOATS / 4; i += C2_THREADS)
            cpa16(wba[0] + i * 16, wp0 + i * 16);
    }
    CP_COMMIT();
    // group 1: weight chunk 1
    {
        const char* wp1 = (const char*)(g_K2 + C2_W_FLOATS);
        for (int i = t; i < C2_W_FLOATS / 4; i += C2_THREADS)
            cpa16(wba[1] + i * 16, wp1 + i * 16);
    }
    CP_COMMIT();

    int yp = t / 64;     // 0..6
    int co = t % 64;     // 0..63
    int prow0 = 2 * yp;

    float acc0[14], acc1[14];
#pragma unroll
    for (int i = 0; i < 14; i++) { acc0[i] = 0.f; acc1[i] = 0.f; }

    for (int chunk = 0; chunk < C2_NCHUNK; chunk++) {
        CP_WAIT1();          // group for this chunk (and input) complete
        __syncthreads();

        const float* ws = wbuf[chunk & 1];
#pragma unroll 1
        for (int cil = 0; cil < C2_WCHUNK_CI; cil++) {
            int ci = chunk * C2_WCHUNK_CI + cil;
            const float* inc = in_s + ci * P1A;
            const float* wp  = ws + (cil * 64 + co) * 25;

#pragma unroll
            for (int j = 0; j < 6; j++) {
                float row[18];
                const float* rp = inc + (prow0 + j) * P1C;
#pragma unroll
                for (int c = 0; c < 18; c++) row[c] = rp[c];

                if (j < 5) {
#pragma unroll
                    for (int kx = 0; kx < 5; kx++) {
                        float wv = wp[j * 5 + kx];
#pragma unroll
                        for (int xx = 0; xx < 14; xx++)
                            acc0[xx] += wv * row[xx + kx];
                    }
                }
                if (j >= 1) {
#pragma unroll
                    for (int kx = 0; kx < 5; kx++) {
                        float wv = wp[(j - 1) * 5 + kx];
#pragma unroll
                        for (int xx = 0; xx < 14; xx++)
                            acc1[xx] += wv * row[xx + kx];
                    }
                }
            }
        }
        __syncthreads();     // all reads of wbuf[chunk&1] done

        // prefetch chunk+2 into the buffer just freed
        if (chunk + 2 < C2_NCHUNK) {
            const char* wn = (const char*)(g_K2 + (chunk + 2) * C2_W_FLOATS);
            unsigned dst = wba[chunk & 1];
            for (int i = t; i < C2_W_FLOATS / 4; i += C2_THREADS)
                cpa16(dst + i * 16, wn + i * 16);
        }
        CP_COMMIT();         // commit (possibly empty) to keep group accounting uniform
    }

    float bias = b2[co];
    float* op = g_pool2 + (b * 64 + co) * 49 + yp * 7;
#pragma unroll
    for (int xp = 0; xp < 7; xp++) {
        float m = fmaxf(fmaxf(acc0[2 * xp], acc0[2 * xp + 1]),
                        fmaxf(acc1[2 * xp], acc1[2 * xp + 1]));
        op[xp] = fmaxf(m + bias, 0.f);
    }
}

// ---------------------------------------------------------------------------
// Kernel 5: fc1 GEMM  C[4096,128] = pool2[4096,3136] @ Wt[3136,128] + b, relu
// ---------------------------------------------------------------------------
__global__ __launch_bounds__(256) void fc1_k(const float* __restrict__ fc1_b) {
    __shared__ float As[32 * 32];
    __shared__ float Bs[32 * 128];

    int m0 = blockIdx.x * 32;
    int tid = threadIdx.x;
    int tm = tid / 32;
    int tn = tid % 32;

    float c[4][4];
#pragma unroll
    for (int i = 0; i < 4; i++)
#pragma unroll
        for (int j = 0; j < 4; j++) c[i][j] = 0.f;

    const float* A = g_pool2;

    for (int k0 = 0; k0 < 3136; k0 += 32) {
#pragma unroll
        for (int l = 0; l < 4; l++) {
            int i = tid + l * 256;
            int mm = i / 32, kk = i % 32;
            As[mm * 32 + kk] = A[(m0 + mm) * 3136 + k0 + kk];
        }
#pragma unroll
        for (int l = 0; l < 16; l++) {
            int i = tid + l * 256;
            int kk = i / 128, n = i % 128;
            Bs[kk * 128 + n] = g_fc1wt[(k0 + kk) * 128 + n];
        }
        __syncthreads();

#pragma unroll
        for (int kk = 0; kk < 32; kk++) {
            float a0 = As[(tm * 4 + 0) * 32 + kk];
            float a1 = As[(tm * 4 + 1) * 32 + kk];
            float a2 = As[(tm * 4 + 2) * 32 + kk];
            float a3 = As[(tm * 4 + 3) * 32 + kk];
            float4 bv = *(const float4*)&Bs[kk * 128 + tn * 4];
            c[0][0] += a0 * bv.x; c[0][1] += a0 * bv.y; c[0][2] += a0 * bv.z; c[0][3] += a0 * bv.w;
            c[1][0] += a1 * bv.x; c[1][1] += a1 * bv.y; c[1][2] += a1 * bv.z; c[1][3] += a1 * bv.w;
            c[2][0] += a2 * bv.x; c[2][1] += a2 * bv.y; c[2][2] += a2 * bv.z; c[2][3] += a2 * bv.w;
            c[3][0] += a3 * bv.x; c[3][1] += a3 * bv.y; c[3][2] += a3 * bv.z; c[3][3] += a3 * bv.w;
        }
        __syncthreads();
    }

#pragma unroll
    for (int j = 0; j < 4; j++) {
        int m = m0 + tm * 4 + j;
#pragma unroll
        for (int jj = 0; jj < 4; jj++) {
            int n = tn * 4 + jj;
            g_fc1o[m * 128 + n] = fmaxf(c[j][jj] + fc1_b[n], 0.f);
        }
    }
}

// ---------------------------------------------------------------------------
// Kernel 6: fc2  out[4096,10] = fc1o[4096,128] @ fc2_w[10,128]^T + b
// ---------------------------------------------------------------------------
__global__ __launch_bounds__(256) void fc2_k(const float* __restrict__ fc2_w,
                                             const float* __restrict__ fc2_b,
                                             float* __restrict__ out) {
    int idx = blockIdx.x * blockDim.x + threadIdx.x;
    if (idx >= NB * 10) return;
    int m = idx / 10, n = idx % 10;
    const float4* h = (const float4*)(g_fc1o + m * 128);
    const float4* w = (const float4*)(fc2_w + n * 128);
    float s = 0.f;
#pragma unroll
    for (int i = 0; i < 32; i++) {
        float4 a = h[i], bb = w[i];
        s += a.x * bb.x + a.y * bb.y + a.z * bb.z + a.w * bb.w;
    }
    out[idx] = s + fc2_b[n];
}

// ---------------------------------------------------------------------------
// Launch
// ---------------------------------------------------------------------------
extern "C" void kernel_launch(void* const* d_in, const int* in_sizes, int n_in,
                              void* d_out, int out_size) {
    const float* x     = (const float*)d_in[0];
    const float* w1    = (const float*)d_in[1];
    const float* p1    = (const float*)d_in[2];
    const float* b1    = (const float*)d_in[3];
    const float* w2    = (const float*)d_in[4];
    const float* p2    = (const float*)d_in[5];
    const float* b2    = (const float*)d_in[6];
    const float* fc1w  = (const float*)d_in[7];
    const float* fc1b  = (const float*)d_in[8];
    const float* fc2w  = (const float*)d_in[9];
    const float* fc2b  = (const float*)d_in[10];
    float* out = (float*)d_out;

    cudaFuncSetAttribute(conv2_k, cudaFuncAttributeMaxDynamicSharedMemorySize,
                         C2_SMEM_FLOATS * 4);

    build_kernels_k<<<(32 + 64 * 32 + 127) / 128, 128>>>(w1, p1, w2, p2);
    transpose_fc1w_k<<<(3136 * 128 + 255) / 256, 256>>>(fc1w);
    conv1_k<<<NB, 256>>>(x, b1);
    conv2_k<<<NB, C2_THREADS, C2_SMEM_FLOATS * 4>>>(b2);
    fc1_k<<<NB / 32, 256>>>(fc1b);
    fc2_k<<<(NB * 10 + 255) / 256, 256>>>(fc2w, fc2b, out);
}